// round 1
// baseline (speedup 1.0000x reference)
#include <cuda_runtime.h>
#include <math.h>

#define BB 4
#define DD 256
#define LL 4096
#define NN (BB*LL)      // 16384 tokens
#define KK 8192
#define EPSF 1e-12f

#define BM 64
#define BN 128
#define AS_LD 68        // 256 x 68 floats (d-major, padded)
#define BS_LD 132       // 256 x 132 floats (d-major, padded)
#define SMEM_BYTES ((256*AS_LD + 256*BS_LD) * 4)

// ---- device scratch (no allocations allowed) ----
__device__ float  g_cbn[KK*DD];    // normalized codebook   (8 MB)
__device__ float  g_xn[NN*DD];     // normalized tokens     (16 MB)
__device__ float  g_norm[NN];      // clamped token norms
__device__ int    g_idx[NN];       // argmax indices
__device__ float  g_rot[NN*DD];    // rotated output, token-major (16 MB)
__device__ double g_acc;           // commit-loss accumulator

// ------------------------------------------------------------------
__global__ void init_acc_kernel() { g_acc = 0.0; }

// one warp per codebook row: cn = c / max(||c||, eps)
__global__ void normalize_codebook_kernel(const float* __restrict__ cb) {
    int row  = blockIdx.x * 8 + (threadIdx.x >> 5);
    int lane = threadIdx.x & 31;
    const float4* src = (const float4*)(cb + (size_t)row * DD);
    float4 v0 = src[lane];
    float4 v1 = src[lane + 32];
    float ss = v0.x*v0.x + v0.y*v0.y + v0.z*v0.z + v0.w*v0.w
             + v1.x*v1.x + v1.y*v1.y + v1.z*v1.z + v1.w*v1.w;
    #pragma unroll
    for (int o = 16; o; o >>= 1) ss += __shfl_xor_sync(~0u, ss, o);
    float inv = 1.0f / fmaxf(sqrtf(ss), EPSF);
    float4* dst = (float4*)(g_cbn + (size_t)row * DD);
    v0.x*=inv; v0.y*=inv; v0.z*=inv; v0.w*=inv;
    v1.x*=inv; v1.y*=inv; v1.z*=inv; v1.w*=inv;
    dst[lane] = v0; dst[lane + 32] = v1;
}

// per-token norms: n = b*L + l, reads x[b][d][l] coalesced over l
__global__ void token_norms_kernel(const float* __restrict__ x) {
    int n = blockIdx.x * blockDim.x + threadIdx.x;
    int b = n / LL, l = n % LL;
    const float* p = x + (size_t)b * DD * LL + l;
    float ss = 0.0f;
    #pragma unroll 8
    for (int d = 0; d < DD; d++) { float v = p[(size_t)d * LL]; ss = fmaf(v, v, ss); }
    g_norm[n] = fmaxf(sqrtf(ss), EPSF);
}

// transpose [B,D,L] -> token-major xn[N,D], scaled by 1/norm
__global__ void make_xn_kernel(const float* __restrict__ x) {
    __shared__ float tile[32][33];
    int b = blockIdx.z, l0 = blockIdx.x * 32, d0 = blockIdx.y * 32;
    int tx = threadIdx.x, ty = threadIdx.y;
    #pragma unroll
    for (int q = 0; q < 4; q++) {
        int d = d0 + ty + q * 8;
        tile[ty + q * 8][tx] = x[(size_t)b * DD * LL + (size_t)d * LL + l0 + tx];
    }
    __syncthreads();
    #pragma unroll
    for (int q = 0; q < 4; q++) {
        int l = l0 + ty + q * 8;
        int n = b * LL + l;
        float inv = 1.0f / g_norm[n];
        g_xn[(size_t)n * DD + d0 + tx] = tile[tx][ty + q * 8] * inv;
    }
}

// ------------------------------------------------------------------
// fused fp32 GEMM + row argmax.  BM=64 tokens x full K, BN=128 codes/chunk.
// smem d-major: As[256][68] (broadcast reads), Bs[256][132] (vectorized).
__global__ void __launch_bounds__(256, 1) argmax_gemm_kernel() {
    extern __shared__ float sm[];
    float* As = sm;                 // [d][m]
    float* Bs = sm + 256 * AS_LD;   // [d][n]
    int tid  = threadIdx.x;
    int tidm = tid >> 5;            // warp id 0..7 -> 8 token rows
    int tidn = tid & 31;            // lane -> 4 code cols
    int mbase = blockIdx.x * BM;

    // load A tile once (64 rows x 256 d), transpose to d-major
    {
        int r = tid >> 2;
        int dseg = (tid & 3) * 64;
        const float4* src = (const float4*)(g_xn + ((size_t)(mbase + r)) * DD + dseg);
        #pragma unroll
        for (int i = 0; i < 16; i++) {
            float4 v = src[i];
            int d = dseg + i * 4;
            As[(d + 0) * AS_LD + r] = v.x;
            As[(d + 1) * AS_LD + r] = v.y;
            As[(d + 2) * AS_LD + r] = v.z;
            As[(d + 3) * AS_LD + r] = v.w;
        }
    }

    float bestv[8]; int besti[8];
    #pragma unroll
    for (int i = 0; i < 8; i++) { bestv[i] = -2.0f; besti[i] = 0; }

    for (int kc = 0; kc < KK / BN; kc++) {
        __syncthreads();
        {   // load B chunk (128 codes x 256 d), transpose to d-major
            int r = tid >> 1;
            int dseg = (tid & 1) * 128;
            const float4* src = (const float4*)(g_cbn + ((size_t)(kc * BN + r)) * DD + dseg);
            #pragma unroll
            for (int i = 0; i < 32; i++) {
                float4 v = src[i];
                int d = dseg + i * 4;
                Bs[(d + 0) * BS_LD + r] = v.x;
                Bs[(d + 1) * BS_LD + r] = v.y;
                Bs[(d + 2) * BS_LD + r] = v.z;
                Bs[(d + 3) * BS_LD + r] = v.w;
            }
        }
        __syncthreads();

        float acc[8][4];
        #pragma unroll
        for (int i = 0; i < 8; i++)
            #pragma unroll
            for (int j = 0; j < 4; j++) acc[i][j] = 0.0f;

        #pragma unroll 4
        for (int d = 0; d < DD; d++) {
            float4 bv = *(const float4*)&Bs[d * BS_LD + tidn * 4];
            float4 a0 = *(const float4*)&As[d * AS_LD + tidm * 8];
            float4 a1 = *(const float4*)&As[d * AS_LD + tidm * 8 + 4];
            float a[8] = {a0.x, a0.y, a0.z, a0.w, a1.x, a1.y, a1.z, a1.w};
            float bb[4] = {bv.x, bv.y, bv.z, bv.w};
            #pragma unroll
            for (int i = 0; i < 8; i++)
                #pragma unroll
                for (int j = 0; j < 4; j++)
                    acc[i][j] = fmaf(a[i], bb[j], acc[i][j]);
        }

        #pragma unroll
        for (int i = 0; i < 8; i++)
            #pragma unroll
            for (int j = 0; j < 4; j++) {
                float v = acc[i][j];
                if (v > bestv[i]) { bestv[i] = v; besti[i] = kc * BN + tidn * 4 + j; }
            }
    }

    // cross-lane argmax reduce (first-index tie-break, matches jnp.argmax)
    #pragma unroll
    for (int i = 0; i < 8; i++) {
        float v = bestv[i]; int ix = besti[i];
        #pragma unroll
        for (int o = 16; o; o >>= 1) {
            float ov = __shfl_xor_sync(~0u, v, o);
            int   oi = __shfl_xor_sync(~0u, ix, o);
            if (ov > v || (ov == v && oi < ix)) { v = ov; ix = oi; }
        }
        if (tidn == 0) g_idx[mbase + tidm * 8 + i] = ix;
    }
}

// ------------------------------------------------------------------
// rotation trick + commit-loss partial.  One warp per token.
// rot = xn - 2 (xn.w) w + 2 q0,  w = (xn+q0)/max(||xn+q0||,eps)
__global__ void rotate_kernel() {
    int warp = threadIdx.x >> 5, lane = threadIdx.x & 31;
    int n = blockIdx.x * 8 + warp;
    const float4* xp = (const float4*)(g_xn + (size_t)n * DD);
    float nrm = g_norm[n];
    int idx = g_idx[n];
    const float4* qp = (const float4*)(g_cbn + (size_t)idx * DD);
    float4 x0 = xp[lane], x1 = xp[lane + 32];
    float4 q0 = qp[lane], q1 = qp[lane + 32];
    float s0x = x0.x + q0.x, s0y = x0.y + q0.y, s0z = x0.z + q0.z, s0w = x0.w + q0.w;
    float s1x = x1.x + q1.x, s1y = x1.y + q1.y, s1z = x1.z + q1.z, s1w = x1.w + q1.w;

    float ss = s0x*s0x + s0y*s0y + s0z*s0z + s0w*s0w
             + s1x*s1x + s1y*s1y + s1z*s1z + s1w*s1w;
    float xs = x0.x*s0x + x0.y*s0y + x0.z*s0z + x0.w*s0w
             + x1.x*s1x + x1.y*s1y + x1.z*s1z + x1.w*s1w;
    #pragma unroll
    for (int o = 16; o; o >>= 1) {
        ss += __shfl_xor_sync(~0u, ss, o);
        xs += __shfl_xor_sync(~0u, xs, o);
    }
    float sn = fmaxf(sqrtf(ss), EPSF);
    float t  = xs / sn;              // xn . w
    float c  = 2.0f * t / sn;        // scale for s

    float4 r0, r1;
    r0.x = x0.x - c*s0x + 2.0f*q0.x;  r0.y = x0.y - c*s0y + 2.0f*q0.y;
    r0.z = x0.z - c*s0z + 2.0f*q0.z;  r0.w = x0.w - c*s0w + 2.0f*q0.w;
    r1.x = x1.x - c*s1x + 2.0f*q1.x;  r1.y = x1.y - c*s1y + 2.0f*q1.y;
    r1.z = x1.z - c*s1z + 2.0f*q1.z;  r1.w = x1.w - c*s1w + 2.0f*q1.w;
    float4* rp = (float4*)(g_rot + (size_t)n * DD);
    rp[lane] = r0; rp[lane + 32] = r1;

    // commit: sum (rot - xn*norm)^2
    float d0x = r0.x - x0.x*nrm, d0y = r0.y - x0.y*nrm, d0z = r0.z - x0.z*nrm, d0w = r0.w - x0.w*nrm;
    float d1x = r1.x - x1.x*nrm, d1y = r1.y - x1.y*nrm, d1z = r1.z - x1.z*nrm, d1w = r1.w - x1.w*nrm;
    float cs = d0x*d0x + d0y*d0y + d0z*d0z + d0w*d0w
             + d1x*d1x + d1y*d1y + d1z*d1z + d1w*d1w;
    #pragma unroll
    for (int o = 16; o; o >>= 1) cs += __shfl_xor_sync(~0u, cs, o);
    if (lane == 0) atomicAdd(&g_acc, (double)cs);
}

// rot[N,D] (token-major) -> out [B,D,L]
__global__ void transpose_out_kernel(float* __restrict__ out) {
    __shared__ float tile[32][33];
    int b = blockIdx.z, l0 = blockIdx.x * 32, d0 = blockIdx.y * 32;
    int tx = threadIdx.x, ty = threadIdx.y;
    #pragma unroll
    for (int q = 0; q < 4; q++) {
        int n = b * LL + l0 + ty + q * 8;
        tile[ty + q * 8][tx] = g_rot[(size_t)n * DD + d0 + tx];
    }
    __syncthreads();
    #pragma unroll
    for (int q = 0; q < 4; q++) {
        int d = d0 + ty + q * 8;
        out[(size_t)b * DD * LL + (size_t)d * LL + l0 + tx] = tile[tx][ty + q * 8];
    }
}

__global__ void finalize_kernel(float* __restrict__ out, int out_size) {
    long q = (long)BB * DD * LL;
    float loss = (float)(0.25 * g_acc / (double)((long)NN * DD));
    for (long i = q + threadIdx.x; i < (long)out_size; i += blockDim.x) out[i] = loss;
}

// ------------------------------------------------------------------
extern "C" void kernel_launch(void* const* d_in, const int* in_sizes, int n_in,
                              void* d_out, int out_size) {
    const float* x  = (const float*)d_in[0];   // [4,256,4096]
    const float* cb = (const float*)d_in[1];   // [8192,256]
    float* out = (float*)d_out;

    init_acc_kernel<<<1, 1>>>();
    normalize_codebook_kernel<<<KK / 8, 256>>>(cb);
    token_norms_kernel<<<NN / 256, 256>>>(x);
    make_xn_kernel<<<dim3(LL / 32, DD / 32, BB), dim3(32, 8)>>>(x);

    static int smem_set = 0;
    if (!smem_set) {
        cudaFuncSetAttribute(argmax_gemm_kernel,
                             cudaFuncAttributeMaxDynamicSharedMemorySize, SMEM_BYTES);
        smem_set = 1;
    }
    argmax_gemm_kernel<<<NN / BM, 256, SMEM_BYTES>>>();

    rotate_kernel<<<NN / 8, 256>>>();
    transpose_out_kernel<<<dim3(LL / 32, DD / 32, BB), dim3(32, 8)>>>(out);
    finalize_kernel<<<1, 256>>>(out, out_size);
}

// round 2
// speedup vs baseline: 5.7053x; 5.7053x over previous
#include <cuda_runtime.h>
#include <cuda_bf16.h>
#include <math.h>
#include <stdint.h>

#define BB 4
#define DD 256
#define LL 4096
#define NN (BB*LL)      // 16384 tokens
#define KK 8192
#define EPSF 1e-12f
#define MARGIN 6e-3f

// ---- GEMM tiling ----
#define BM 128
#define BN 128
#define BK 32
#define LDT 56                      // padded row stride in halves (112B, 16B-aligned, conflict-free)
#define TILE_HALVES (128*LDT)       // 7168 halves = 14336 bytes
#define TILE_BYTES  (TILE_HALVES*2)
#define GEMM_SMEM   (4*TILE_BYTES)  // A+B, double buffered = 57344

// ---- device scratch (no allocations allowed) ----
__device__ float          g_cbn[KK*DD];     // normalized codebook fp32 (8 MB)
__device__ float          g_xn[NN*DD];      // normalized tokens fp32 (16 MB)
__device__ __nv_bfloat16  g_ch[KK*DD];      // normalized codebook bf16 (4 MB)
__device__ __nv_bfloat16  g_xh[NN*DD];      // normalized tokens bf16 (8 MB)
__device__ __nv_bfloat16  g_simh[(size_t)NN*KK]; // bf16 sims (268 MB)
__device__ float          g_norm[NN];
__device__ int            g_idx[NN];
__device__ float          g_rot[NN*DD];
__device__ double         g_acc;

// ------------------------------------------------------------------
__global__ void init_acc_kernel() { g_acc = 0.0; }

__device__ __forceinline__ uint32_t pack_bf16x2(float lo, float hi) {
    uint32_t r;
    asm("cvt.rn.bf16x2.f32 %0, %1, %2;" : "=r"(r) : "f"(hi), "f"(lo));
    return r;
}

// one warp per codebook row: cn = c / max(||c||, eps); fp32 + bf16 outputs
__global__ void normalize_codebook_kernel(const float* __restrict__ cb) {
    int row  = blockIdx.x * 8 + (threadIdx.x >> 5);
    int lane = threadIdx.x & 31;
    const float4* src = (const float4*)(cb + (size_t)row * DD);
    float4 v0 = src[lane];
    float4 v1 = src[lane + 32];
    float ss = v0.x*v0.x + v0.y*v0.y + v0.z*v0.z + v0.w*v0.w
             + v1.x*v1.x + v1.y*v1.y + v1.z*v1.z + v1.w*v1.w;
    #pragma unroll
    for (int o = 16; o; o >>= 1) ss += __shfl_xor_sync(~0u, ss, o);
    float inv = 1.0f / fmaxf(sqrtf(ss), EPSF);
    v0.x*=inv; v0.y*=inv; v0.z*=inv; v0.w*=inv;
    v1.x*=inv; v1.y*=inv; v1.z*=inv; v1.w*=inv;
    float4* dst = (float4*)(g_cbn + (size_t)row * DD);
    dst[lane] = v0; dst[lane + 32] = v1;
    uint2* hd = (uint2*)(g_ch + (size_t)row * DD);
    hd[lane]      = make_uint2(pack_bf16x2(v0.x, v0.y), pack_bf16x2(v0.z, v0.w));
    hd[lane + 32] = make_uint2(pack_bf16x2(v1.x, v1.y), pack_bf16x2(v1.z, v1.w));
}

// per-token norms
__global__ void token_norms_kernel(const float* __restrict__ x) {
    int n = blockIdx.x * blockDim.x + threadIdx.x;
    int b = n / LL, l = n % LL;
    const float* p = x + (size_t)b * DD * LL + l;
    float ss = 0.0f;
    #pragma unroll 8
    for (int d = 0; d < DD; d++) { float v = p[(size_t)d * LL]; ss = fmaf(v, v, ss); }
    g_norm[n] = fmaxf(sqrtf(ss), EPSF);
}

// transpose [B,D,L] -> token-major xn[N,D] (fp32 + bf16), scaled by 1/norm
__global__ void make_xn_kernel(const float* __restrict__ x) {
    __shared__ float tile[32][33];
    int b = blockIdx.z, l0 = blockIdx.x * 32, d0 = blockIdx.y * 32;
    int tx = threadIdx.x, ty = threadIdx.y;
    #pragma unroll
    for (int q = 0; q < 4; q++) {
        int d = d0 + ty + q * 8;
        tile[ty + q * 8][tx] = x[(size_t)b * DD * LL + (size_t)d * LL + l0 + tx];
    }
    __syncthreads();
    #pragma unroll
    for (int q = 0; q < 4; q++) {
        int l = l0 + ty + q * 8;
        int n = b * LL + l;
        float inv = 1.0f / g_norm[n];
        float v = tile[tx][ty + q * 8] * inv;
        g_xn[(size_t)n * DD + d0 + tx] = v;
        g_xh[(size_t)n * DD + d0 + tx] = __float2bfloat16(v);
    }
}

// ------------------------------------------------------------------
// bf16 tensor-core GEMM: sims[N,K] = xn @ cn^T  (fp32 accum, bf16 out)
#define CP_ASYNC16(dst, src) \
    asm volatile("cp.async.cg.shared.global [%0], [%1], 16;\n" :: "r"(dst), "l"(src))

__device__ __forceinline__ void load_tile(int kt, int buf, uint32_t smem_u32,
                                          const __nv_bfloat16* A,
                                          const __nv_bfloat16* B, int tid) {
    #pragma unroll
    for (int i = 0; i < 2; i++) {
        int idx = tid + i * 256;
        int row = idx >> 2;
        int kc  = (idx & 3) * 8;
        uint32_t dA = smem_u32 + buf * (2*TILE_BYTES) + (row * LDT + kc) * 2;
        CP_ASYNC16(dA, A + (size_t)row * DD + kt * BK + kc);
        uint32_t dB = dA + TILE_BYTES;
        CP_ASYNC16(dB, B + (size_t)row * DD + kt * BK + kc);
    }
}

__global__ void __launch_bounds__(256) gemm_bf16_kernel() {
    extern __shared__ __nv_bfloat16 sm[];
    uint32_t smem_u32 = (uint32_t)__cvta_generic_to_shared(sm);
    int tid = threadIdx.x;
    int wid = tid >> 5, lane = tid & 31;
    int warp_m = wid & 3, warp_n = wid >> 2;     // 4x2 warp grid, 32x64 per warp
    int grp = lane >> 2, qid = lane & 3;
    int nbase = blockIdx.x * BN;
    int mbase = blockIdx.y * BM;
    const __nv_bfloat16* Ag = g_xh + (size_t)mbase * DD;
    const __nv_bfloat16* Bg = g_ch + (size_t)nbase * DD;

    float c[2][8][4];
    #pragma unroll
    for (int mi = 0; mi < 2; mi++)
        #pragma unroll
        for (int ni = 0; ni < 8; ni++)
            #pragma unroll
            for (int j = 0; j < 4; j++) c[mi][ni][j] = 0.0f;

    load_tile(0, 0, smem_u32, Ag, Bg, tid);
    asm volatile("cp.async.commit_group;\n" ::);

    for (int kt = 0; kt < DD / BK; kt++) {
        if (kt < DD / BK - 1) {
            load_tile(kt + 1, (kt + 1) & 1, smem_u32, Ag, Bg, tid);
            asm volatile("cp.async.commit_group;\n" ::);
            asm volatile("cp.async.wait_group 1;\n" ::);
        } else {
            asm volatile("cp.async.wait_group 0;\n" ::);
        }
        __syncthreads();

        const __nv_bfloat16* sA = sm + (kt & 1) * (2 * TILE_HALVES);
        const __nv_bfloat16* sB = sA + TILE_HALVES;
        #pragma unroll
        for (int ks = 0; ks < BK; ks += 16) {
            uint32_t a[2][4], b[8][2];
            #pragma unroll
            for (int mi = 0; mi < 2; mi++) {
                const __nv_bfloat16* pa = sA + (warp_m*32 + mi*16 + grp) * LDT + ks + qid*2;
                a[mi][0] = *(const uint32_t*)(pa);
                a[mi][1] = *(const uint32_t*)(pa + 8*LDT);
                a[mi][2] = *(const uint32_t*)(pa + 8);
                a[mi][3] = *(const uint32_t*)(pa + 8*LDT + 8);
            }
            #pragma unroll
            for (int ni = 0; ni < 8; ni++) {
                const __nv_bfloat16* pb = sB + (warp_n*64 + ni*8 + grp) * LDT + ks + qid*2;
                b[ni][0] = *(const uint32_t*)(pb);
                b[ni][1] = *(const uint32_t*)(pb + 8);
            }
            #pragma unroll
            for (int mi = 0; mi < 2; mi++)
                #pragma unroll
                for (int ni = 0; ni < 8; ni++)
                    asm volatile(
                        "mma.sync.aligned.m16n8k16.row.col.f32.bf16.bf16.f32 "
                        "{%0,%1,%2,%3}, {%4,%5,%6,%7}, {%8,%9}, {%0,%1,%2,%3};\n"
                        : "+f"(c[mi][ni][0]), "+f"(c[mi][ni][1]),
                          "+f"(c[mi][ni][2]), "+f"(c[mi][ni][3])
                        : "r"(a[mi][0]), "r"(a[mi][1]), "r"(a[mi][2]), "r"(a[mi][3]),
                          "r"(b[ni][0]), "r"(b[ni][1]));
        }
        __syncthreads();
    }

    // epilogue: bf16 pair stores
    #pragma unroll
    for (int mi = 0; mi < 2; mi++)
        #pragma unroll
        for (int ni = 0; ni < 8; ni++) {
            int row = mbase + warp_m*32 + mi*16 + grp;
            int col = nbase + warp_n*64 + ni*8 + qid*2;
            *(uint32_t*)&g_simh[(size_t)row * KK + col] =
                pack_bf16x2(c[mi][ni][0], c[mi][ni][1]);
            *(uint32_t*)&g_simh[(size_t)(row + 8) * KK + col] =
                pack_bf16x2(c[mi][ni][2], c[mi][ni][3]);
        }
}

// ------------------------------------------------------------------
// per-token: bf16 max -> candidate set within MARGIN -> exact fp32 rescore
__global__ void select_kernel() {
    __shared__ int cnt[8];
    __shared__ int cand[8][64];
    int wid = threadIdx.x >> 5, lane = threadIdx.x & 31;
    int n = blockIdx.x * 8 + wid;
    const uint4* rowp = (const uint4*)(g_simh + (size_t)n * KK);  // 1024 x 16B

    float mx = -2.0f;
    #pragma unroll 4
    for (int cidx = lane; cidx < KK/8; cidx += 32) {
        uint4 v = rowp[cidx];
        float2 f0 = __bfloat1622float2(*(const __nv_bfloat162*)&v.x);
        float2 f1 = __bfloat1622float2(*(const __nv_bfloat162*)&v.y);
        float2 f2 = __bfloat1622float2(*(const __nv_bfloat162*)&v.z);
        float2 f3 = __bfloat1622float2(*(const __nv_bfloat162*)&v.w);
        mx = fmaxf(mx, fmaxf(fmaxf(fmaxf(f0.x, f0.y), fmaxf(f1.x, f1.y)),
                             fmaxf(fmaxf(f2.x, f2.y), fmaxf(f3.x, f3.y))));
    }
    #pragma unroll
    for (int o = 16; o; o >>= 1) mx = fmaxf(mx, __shfl_xor_sync(~0u, mx, o));
    float thr = mx - MARGIN;

    if (lane == 0) cnt[wid] = 0;
    __syncwarp();
    #pragma unroll 4
    for (int cidx = lane; cidx < KK/8; cidx += 32) {
        uint4 v = rowp[cidx];
        float f[8];
        *(float2*)&f[0] = __bfloat1622float2(*(const __nv_bfloat162*)&v.x);
        *(float2*)&f[2] = __bfloat1622float2(*(const __nv_bfloat162*)&v.y);
        *(float2*)&f[4] = __bfloat1622float2(*(const __nv_bfloat162*)&v.z);
        *(float2*)&f[6] = __bfloat1622float2(*(const __nv_bfloat162*)&v.w);
        #pragma unroll
        for (int j = 0; j < 8; j++)
            if (f[j] >= thr) {
                int p = atomicAdd(&cnt[wid], 1);
                if (p < 64) cand[wid][p] = cidx * 8 + j;
            }
    }
    __syncwarp();
    int m = cnt[wid]; if (m > 64) m = 64;

    // exact fp32 rescore of candidates
    const float4* xp = (const float4*)(g_xn + (size_t)n * DD);
    float4 x0 = xp[lane * 2], x1 = xp[lane * 2 + 1];
    float bestv = -2.0f; int besti = 0x7fffffff;
    for (int ci = 0; ci < m; ci++) {
        int k = cand[wid][ci];
        const float4* cp = (const float4*)(g_cbn + (size_t)k * DD);
        float4 c0 = cp[lane * 2], c1 = cp[lane * 2 + 1];
        float d = x0.x*c0.x + x0.y*c0.y + x0.z*c0.z + x0.w*c0.w
                + x1.x*c1.x + x1.y*c1.y + x1.z*c1.z + x1.w*c1.w;
        #pragma unroll
        for (int o = 16; o; o >>= 1) d += __shfl_xor_sync(~0u, d, o);
        if (d > bestv || (d == bestv && k < besti)) { bestv = d; besti = k; }
    }
    if (lane == 0) g_idx[n] = besti;
}

// ------------------------------------------------------------------
// rotation trick + commit-loss partial (one warp per token)
__global__ void rotate_kernel() {
    int warp = threadIdx.x >> 5, lane = threadIdx.x & 31;
    int n = blockIdx.x * 8 + warp;
    const float4* xp = (const float4*)(g_xn + (size_t)n * DD);
    float nrm = g_norm[n];
    int idx = g_idx[n];
    const float4* qp = (const float4*)(g_cbn + (size_t)idx * DD);
    float4 x0 = xp[lane], x1 = xp[lane + 32];
    float4 q0 = qp[lane], q1 = qp[lane + 32];
    float s0x = x0.x + q0.x, s0y = x0.y + q0.y, s0z = x0.z + q0.z, s0w = x0.w + q0.w;
    float s1x = x1.x + q1.x, s1y = x1.y + q1.y, s1z = x1.z + q1.z, s1w = x1.w + q1.w;

    float ss = s0x*s0x + s0y*s0y + s0z*s0z + s0w*s0w
             + s1x*s1x + s1y*s1y + s1z*s1z + s1w*s1w;
    float xs = x0.x*s0x + x0.y*s0y + x0.z*s0z + x0.w*s0w
             + x1.x*s1x + x1.y*s1y + x1.z*s1z + x1.w*s1w;
    #pragma unroll
    for (int o = 16; o; o >>= 1) {
        ss += __shfl_xor_sync(~0u, ss, o);
        xs += __shfl_xor_sync(~0u, xs, o);
    }
    float sn = fmaxf(sqrtf(ss), EPSF);
    float t  = xs / sn;
    float c  = 2.0f * t / sn;

    float4 r0, r1;
    r0.x = x0.x - c*s0x + 2.0f*q0.x;  r0.y = x0.y - c*s0y + 2.0f*q0.y;
    r0.z = x0.z - c*s0z + 2.0f*q0.z;  r0.w = x0.w - c*s0w + 2.0f*q0.w;
    r1.x = x1.x - c*s1x + 2.0f*q1.x;  r1.y = x1.y - c*s1y + 2.0f*q1.y;
    r1.z = x1.z - c*s1z + 2.0f*q1.z;  r1.w = x1.w - c*s1w + 2.0f*q1.w;
    float4* rp = (float4*)(g_rot + (size_t)n * DD);
    rp[lane] = r0; rp[lane + 32] = r1;

    float d0x = r0.x - x0.x*nrm, d0y = r0.y - x0.y*nrm, d0z = r0.z - x0.z*nrm, d0w = r0.w - x0.w*nrm;
    float d1x = r1.x - x1.x*nrm, d1y = r1.y - x1.y*nrm, d1z = r1.z - x1.z*nrm, d1w = r1.w - x1.w*nrm;
    float cs = d0x*d0x + d0y*d0y + d0z*d0z + d0w*d0w
             + d1x*d1x + d1y*d1y + d1z*d1z + d1w*d1w;
    #pragma unroll
    for (int o = 16; o; o >>= 1) cs += __shfl_xor_sync(~0u, cs, o);
    if (lane == 0) atomicAdd(&g_acc, (double)cs);
}

// rot[N,D] (token-major) -> out [B,D,L]
__global__ void transpose_out_kernel(float* __restrict__ out) {
    __shared__ float tile[32][33];
    int b = blockIdx.z, l0 = blockIdx.x * 32, d0 = blockIdx.y * 32;
    int tx = threadIdx.x, ty = threadIdx.y;
    #pragma unroll
    for (int q = 0; q < 4; q++) {
        int n = b * LL + l0 + ty + q * 8;
        tile[ty + q * 8][tx] = g_rot[(size_t)n * DD + d0 + tx];
    }
    __syncthreads();
    #pragma unroll
    for (int q = 0; q < 4; q++) {
        int d = d0 + ty + q * 8;
        out[(size_t)b * DD * LL + (size_t)d * LL + l0 + tx] = tile[tx][ty + q * 8];
    }
}

__global__ void finalize_kernel(float* __restrict__ out, int out_size) {
    long q = (long)BB * DD * LL;
    float loss = (float)(0.25 * g_acc / (double)((long)NN * DD));
    for (long i = q + threadIdx.x; i < (long)out_size; i += blockDim.x) out[i] = loss;
}

// ------------------------------------------------------------------
extern "C" void kernel_launch(void* const* d_in, const int* in_sizes, int n_in,
                              void* d_out, int out_size) {
    const float* x  = (const float*)d_in[0];   // [4,256,4096]
    const float* cb = (const float*)d_in[1];   // [8192,256]
    float* out = (float*)d_out;

    static int attr_set = 0;
    if (!attr_set) {
        cudaFuncSetAttribute(gemm_bf16_kernel,
                             cudaFuncAttributeMaxDynamicSharedMemorySize, GEMM_SMEM);
        attr_set = 1;
    }

    init_acc_kernel<<<1, 1>>>();
    normalize_codebook_kernel<<<KK / 8, 256>>>(cb);
    token_norms_kernel<<<NN / 256, 256>>>(x);
    make_xn_kernel<<<dim3(LL / 32, DD / 32, BB), dim3(32, 8)>>>(x);

    gemm_bf16_kernel<<<dim3(KK / BN, NN / BM), 256, GEMM_SMEM>>>();
    select_kernel<<<NN / 8, 256>>>();

    rotate_kernel<<<NN / 8, 256>>>();
    transpose_out_kernel<<<dim3(LL / 32, DD / 32, BB), dim3(32, 8)>>>(out);
    finalize_kernel<<<1, 256>>>(out, out_size);
}